// round 3
// baseline (speedup 1.0000x reference)
#include <cuda_runtime.h>
#include <cuda_bf16.h>
#include <cstdint>

#define HID   512
#define SRC   2048
#define BATCH 64
#define KC    32          // K-chunk per SMEM stage
#define LDSM_STRIDE (KC + 8)   // 40 bf16 elems per row -> 80B row stride, ldmatrix conflict-free

// ---------------- device scratch (no allocations allowed) ----------------
__device__ __align__(16) __nv_bfloat16 g_W1hi[HID * HID];
__device__ __align__(16) __nv_bfloat16 g_W1lo[HID * HID];
__device__ float g_cbias[BATCH * HID];          // W1_b + W2_b + h@W2^T
__device__ float g_part[4][BATCH][SRC];         // per-n-block partial scores

// ---------------- helpers ----------------
__device__ __forceinline__ unsigned smem_u32(const void* p) {
    return (unsigned)__cvta_generic_to_shared(p);
}

__device__ __forceinline__ void ldsm4(uint32_t r[4], unsigned addr) {
    asm volatile("ldmatrix.sync.aligned.m8n8.x4.shared.b16 {%0,%1,%2,%3}, [%4];"
                 : "=r"(r[0]), "=r"(r[1]), "=r"(r[2]), "=r"(r[3]) : "r"(addr));
}

__device__ __forceinline__ void mma_bf16(float c[4], const uint32_t a[4], const uint32_t b[2]) {
    asm volatile(
        "mma.sync.aligned.m16n8k16.row.col.f32.bf16.bf16.f32 "
        "{%0,%1,%2,%3}, {%4,%5,%6,%7}, {%8,%9}, {%0,%1,%2,%3};"
        : "+f"(c[0]), "+f"(c[1]), "+f"(c[2]), "+f"(c[3])
        : "r"(a[0]), "r"(a[1]), "r"(a[2]), "r"(a[3]), "r"(b[0]), "r"(b[1]));
}

// ---------------- kernel 1: split W1 into bf16 hi/lo ----------------
__global__ void prep_w_kernel(const float* __restrict__ W1w) {
    int i = blockIdx.x * blockDim.x + threadIdx.x;
    if (i < HID * HID) {
        float w = W1w[i];
        __nv_bfloat16 hi = __float2bfloat16(w);
        float lo = w - __bfloat162float(hi);
        g_W1hi[i] = hi;
        g_W1lo[i] = __float2bfloat16(lo);
    }
}

// ---------------- kernel 2: cbias[b][o] = W1_b[o] + W2_b[o] + sum_k h[b][k]*W2[o][k] ----------------
__global__ void cbias_kernel(const float* __restrict__ h,
                             const float* __restrict__ W2w,
                             const float* __restrict__ W2b,
                             const float* __restrict__ W1b) {
    __shared__ float hs[HID];
    int b = blockIdx.x;
    int o = threadIdx.x;                 // 512 threads
    hs[o] = h[b * HID + o];
    __syncthreads();
    float acc = W2b[o] + W1b[o];
    const float* wr = W2w + o * HID;
#pragma unroll 8
    for (int k = 0; k < HID; k++) acc += hs[k] * wr[k];
    g_cbias[b * HID + o] = acc;
}

// ---------------- kernel 3: fused GEMM(3x bf16 split) + tanh + V-dot ----------------
// grid: (4 n-blocks, 16 s-tiles, 64 batch), 256 threads (8 warps: 4 along M x 2 along N)
// CTA tile: M=128 (s), N=128 (o), K=512 streamed in chunks of KC=32.
__global__ __launch_bounds__(256) void attn_main_kernel(const float* __restrict__ enc,
                                                        const float* __restrict__ Vw) {
    __shared__ __align__(16) __nv_bfloat16 sAhi[128 * LDSM_STRIDE];
    __shared__ __align__(16) __nv_bfloat16 sAlo[128 * LDSM_STRIDE];
    __shared__ __align__(16) __nv_bfloat16 sBhi[128 * LDSM_STRIDE];
    __shared__ __align__(16) __nv_bfloat16 sBlo[128 * LDSM_STRIDE];
    __shared__ float sCb[128];
    __shared__ float sV[128];
    __shared__ float sRed[128 * 2];

    const int nb  = blockIdx.x;          // n-block (0..3), fastest-varying -> L2 reuse of enc tile
    const int st  = blockIdx.y;          // s-tile (0..15)
    const int b   = blockIdx.z;          // batch
    const int tid = threadIdx.x;
    const int lane = tid & 31;
    const int wid  = tid >> 5;
    const int warp_m = wid & 3;          // 4 warps along M (32 rows each)
    const int warp_n = wid >> 2;         // 2 warps along N (64 cols each)

    if (tid < 128) {
        sCb[tid] = g_cbias[b * HID + nb * 128 + tid];
        sV[tid]  = Vw[nb * 128 + tid];
    }

    float acc[2][8][4];
#pragma unroll
    for (int i = 0; i < 2; i++)
#pragma unroll
        for (int j = 0; j < 8; j++)
#pragma unroll
            for (int r = 0; r < 4; r++) acc[i][j][r] = 0.f;

    const int s0 = st * 128;
    const int o0 = nb * 128;

    for (int kc = 0; kc < HID; kc += KC) {
        if (kc) __syncthreads();

        // --- load A (enc fp32 128xKC) with on-the-fly hi/lo split ---
        // 128 rows * 8 float4/row = 1024 float4 ; 4 per thread
#pragma unroll
        for (int i = 0; i < 4; i++) {
            int idx = tid + i * 256;
            int row = idx >> 3;           // /8
            int c4  = idx & 7;            // float4 index within row
            const float4 f4 = *reinterpret_cast<const float4*>(
                enc + ((size_t)(b * SRC + s0 + row)) * HID + kc + c4 * 4);
            __nv_bfloat162 h0 = __floats2bfloat162_rn(f4.x, f4.y);
            __nv_bfloat162 h1 = __floats2bfloat162_rn(f4.z, f4.w);
            float2 hf0 = __bfloat1622float2(h0);
            float2 hf1 = __bfloat1622float2(h1);
            __nv_bfloat162 l0 = __floats2bfloat162_rn(f4.x - hf0.x, f4.y - hf0.y);
            __nv_bfloat162 l1 = __floats2bfloat162_rn(f4.z - hf1.x, f4.w - hf1.y);
            int soff = row * LDSM_STRIDE + c4 * 4;
            *reinterpret_cast<__nv_bfloat162*>(&sAhi[soff])     = h0;
            *reinterpret_cast<__nv_bfloat162*>(&sAhi[soff + 2]) = h1;
            *reinterpret_cast<__nv_bfloat162*>(&sAlo[soff])     = l0;
            *reinterpret_cast<__nv_bfloat162*>(&sAlo[soff + 2]) = l1;
        }

        // --- load W hi/lo (bf16 128xKC): 128 rows * 4 uint4/row = 512 uint4 each ---
#pragma unroll
        for (int i = 0; i < 2; i++) {
            int idx = tid + i * 256;
            int row = idx >> 2;           // /4
            int c8  = idx & 3;            // 8-elem unit
            size_t goff = (size_t)(o0 + row) * HID + kc + c8 * 8;
            int soff = row * LDSM_STRIDE + c8 * 8;
            *reinterpret_cast<uint4*>(&sBhi[soff]) =
                *reinterpret_cast<const uint4*>(&g_W1hi[goff]);
            *reinterpret_cast<uint4*>(&sBlo[soff]) =
                *reinterpret_cast<const uint4*>(&g_W1lo[goff]);
        }
        __syncthreads();

        // --- compute: 2 k16 steps per chunk ---
#pragma unroll
        for (int ks = 0; ks < KC; ks += 16) {
            uint32_t ah[2][4], al[2][4];
#pragma unroll
            for (int mt = 0; mt < 2; mt++) {
                int r = warp_m * 32 + mt * 16 + (lane & 15);
                int c = ks + ((lane >> 4) << 3);
                ldsm4(ah[mt], smem_u32(&sAhi[r * LDSM_STRIDE + c]));
                ldsm4(al[mt], smem_u32(&sAlo[r * LDSM_STRIDE + c]));
            }
#pragma unroll
            for (int ntp = 0; ntp < 4; ntp++) {
                int br = warp_n * 64 + ntp * 16 + ((lane >> 4) << 3) + (lane & 7);
                int bc = ks + (((lane >> 3) & 1) << 3);
                uint32_t bh[4], bl[4];
                ldsm4(bh, smem_u32(&sBhi[br * LDSM_STRIDE + bc]));
                ldsm4(bl, smem_u32(&sBlo[br * LDSM_STRIDE + bc]));
#pragma unroll
                for (int mt = 0; mt < 2; mt++) {
#pragma unroll
                    for (int half = 0; half < 2; half++) {
                        float* c = acc[mt][ntp * 2 + half];
                        mma_bf16(c, ah[mt], bh + 2 * half);   // hi*hi
                        mma_bf16(c, al[mt], bh + 2 * half);   // lo*hi
                        mma_bf16(c, ah[mt], bl + 2 * half);   // hi*lo
                    }
                }
            }
        }
    }

    // --- epilogue: tanh(acc + cbias) * V, reduce over N ---
    float rowsum[2][2];
    rowsum[0][0] = rowsum[0][1] = rowsum[1][0] = rowsum[1][1] = 0.f;

#pragma unroll
    for (int mt = 0; mt < 2; mt++) {
#pragma unroll
        for (int nt = 0; nt < 8; nt++) {
            int ln = warp_n * 64 + nt * 8 + (lane & 3) * 2;   // local n index in [0,128)
            float cb0 = sCb[ln],     v0 = sV[ln];
            float cb1 = sCb[ln + 1], v1 = sV[ln + 1];
            rowsum[mt][0] += tanhf(acc[mt][nt][0] + cb0) * v0;
            rowsum[mt][0] += tanhf(acc[mt][nt][1] + cb1) * v1;
            rowsum[mt][1] += tanhf(acc[mt][nt][2] + cb0) * v0;
            rowsum[mt][1] += tanhf(acc[mt][nt][3] + cb1) * v1;
        }
    }

    // reduce across the 4 lanes sharing a row
#pragma unroll
    for (int mt = 0; mt < 2; mt++) {
#pragma unroll
        for (int j = 0; j < 2; j++) {
            float v = rowsum[mt][j];
            v += __shfl_xor_sync(0xffffffffu, v, 1);
            v += __shfl_xor_sync(0xffffffffu, v, 2);
            if ((lane & 3) == 0) {
                int row = warp_m * 32 + mt * 16 + (lane >> 2) + 8 * j;
                sRed[row * 2 + warp_n] = v;
            }
        }
    }
    __syncthreads();

    if (tid < 128) {
        g_part[nb][b][s0 + tid] = sRed[tid * 2] + sRed[tid * 2 + 1];
    }
}

// ---------------- kernel 4: sum partials + softmax over S ----------------
__global__ void softmax_kernel(float* __restrict__ out) {
    __shared__ float sv[SRC];
    __shared__ float red[256];
    int b = blockIdx.x;
    int tid = threadIdx.x;

    float mx = -1e30f;
    for (int s = tid; s < SRC; s += 256) {
        float v = g_part[0][b][s] + g_part[1][b][s] + g_part[2][b][s] + g_part[3][b][s];
        sv[s] = v;
        mx = fmaxf(mx, v);
    }
    red[tid] = mx;
    __syncthreads();
    for (int st = 128; st > 0; st >>= 1) {
        if (tid < st) red[tid] = fmaxf(red[tid], red[tid + st]);
        __syncthreads();
    }
    mx = red[0];
    __syncthreads();

    float sum = 0.f;
    for (int s = tid; s < SRC; s += 256) {
        float e = expf(sv[s] - mx);
        sv[s] = e;
        sum += e;
    }
    red[tid] = sum;
    __syncthreads();
    for (int st = 128; st > 0; st >>= 1) {
        if (tid < st) red[tid] += red[tid + st];
        __syncthreads();
    }
    float inv = 1.0f / red[0];
    __syncthreads();

    for (int s = tid; s < SRC; s += 256) {
        out[(size_t)b * SRC + s] = sv[s] * inv;
    }
}

// ---------------- launch ----------------
extern "C" void kernel_launch(void* const* d_in, const int* in_sizes, int n_in,
                              void* d_out, int out_size) {
    const float* h    = (const float*)d_in[0];   // [1, 64, 512]
    const float* enc  = (const float*)d_in[1];   // [64, 2048, 512]
    const float* W1w  = (const float*)d_in[2];   // [512, 512]
    const float* W1b  = (const float*)d_in[3];   // [512]
    const float* W2w  = (const float*)d_in[4];   // [512, 512]
    const float* W2b  = (const float*)d_in[5];   // [512]
    const float* Vw   = (const float*)d_in[6];   // [1, 512]
    // d_in[7] = V_b : constant shift, softmax-invariant -> unused
    float* out = (float*)d_out;                  // [64, 2048]

    prep_w_kernel<<<(HID * HID + 511) / 512, 512>>>(W1w);
    cbias_kernel<<<BATCH, HID>>>(h, W2w, W2b, W1b);
    attn_main_kernel<<<dim3(4, SRC / 128, BATCH), 256>>>(enc, Vw);
    softmax_kernel<<<BATCH, 256>>>(out);
}

// round 7
// speedup vs baseline: 1.2698x; 1.2698x over previous
#include <cuda_runtime.h>
#include <cuda_fp16.h>
#include <cstdint>

#define HID   512
#define SRC   2048
#define BATCH 64

// main kernel tiling
#define KC    64                 // K per pipeline stage
#define LDT   72                 // halves per smem tile row (144B, conflict-free ldsm)
#define LDTB  (LDT * 2)          // 144 bytes
#define TILE_BYTES (128 * LDTB)  // 18432 B per 128-row tile
#define STG_BYTES  (3 * TILE_BYTES)   // A + Bhi + Blo = 55296
#define SMEM_BYTES (2 * STG_BYTES)    // 110592 (double buffered)

// ---------------- device scratch (static, no runtime allocation) ----------------
__device__ __align__(16) __half g_encH[(size_t)BATCH * SRC * HID];  // 128 MB fp16 enc
__device__ __align__(16) __half g_W1hi[HID * HID];
__device__ __align__(16) __half g_W1lo[HID * HID];
__device__ float g_cbias[BATCH * HID];          // W1_b + W2_b + h@W2^T
__device__ float g_part[4][BATCH][SRC];         // per-n-block partial scores

// ---------------- helpers ----------------
__device__ __forceinline__ unsigned smem_u32(const void* p) {
    return (unsigned)__cvta_generic_to_shared(p);
}
__device__ __forceinline__ void ldsm4(uint32_t r[4], unsigned addr) {
    asm volatile("ldmatrix.sync.aligned.m8n8.x4.shared.b16 {%0,%1,%2,%3}, [%4];"
                 : "=r"(r[0]), "=r"(r[1]), "=r"(r[2]), "=r"(r[3]) : "r"(addr));
}
__device__ __forceinline__ void mma_fp16(float c[4], const uint32_t a[4], const uint32_t b[2]) {
    asm volatile(
        "mma.sync.aligned.m16n8k16.row.col.f32.f16.f16.f32 "
        "{%0,%1,%2,%3}, {%4,%5,%6,%7}, {%8,%9}, {%0,%1,%2,%3};"
        : "+f"(c[0]), "+f"(c[1]), "+f"(c[2]), "+f"(c[3])
        : "r"(a[0]), "r"(a[1]), "r"(a[2]), "r"(a[3]), "r"(b[0]), "r"(b[1]));
}
__device__ __forceinline__ void cp_async16(uint32_t dst, const void* src) {
    asm volatile("cp.async.cg.shared.global [%0], [%1], 16;" :: "r"(dst), "l"(src) : "memory");
}
__device__ __forceinline__ void cp_commit() {
    asm volatile("cp.async.commit_group;" ::: "memory");
}

// ---------------- kernel 1a: convert enc fp32 -> fp16 ----------------
__global__ void prep_enc_kernel(const float* __restrict__ enc) {
    const size_t n4 = (size_t)BATCH * SRC * HID / 4;
    size_t i = (size_t)blockIdx.x * blockDim.x + threadIdx.x;
    const size_t stride = (size_t)gridDim.x * blockDim.x;
    for (; i < n4; i += stride) {
        float4 f = reinterpret_cast<const float4*>(enc)[i];
        __half2 h01 = __floats2half2_rn(f.x, f.y);
        __half2 h23 = __floats2half2_rn(f.z, f.w);
        uint2 u;
        u.x = *reinterpret_cast<uint32_t*>(&h01);
        u.y = *reinterpret_cast<uint32_t*>(&h23);
        reinterpret_cast<uint2*>(g_encH)[i] = u;
    }
}

// ---------------- kernel 1b: split W1 into fp16 hi/lo ----------------
__global__ void prep_w_kernel(const float* __restrict__ W1w) {
    int i = blockIdx.x * blockDim.x + threadIdx.x;
    if (i < HID * HID) {
        float w = W1w[i];
        __half hi = __float2half_rn(w);
        float lo = w - __half2float(hi);
        g_W1hi[i] = hi;
        g_W1lo[i] = __float2half_rn(lo);
    }
}

// ---------------- kernel 2: cbias[b][o] = W1_b[o] + W2_b[o] + h[b]@W2[o] ----------------
__global__ void cbias_kernel(const float* __restrict__ h,
                             const float* __restrict__ W2w,
                             const float* __restrict__ W2b,
                             const float* __restrict__ W1b) {
    __shared__ float hs[HID];
    int b = blockIdx.x;
    int o = threadIdx.x;
    hs[o] = h[b * HID + o];
    __syncthreads();
    float acc = W2b[o] + W1b[o];
    const float* wr = W2w + o * HID;
#pragma unroll 8
    for (int k = 0; k < HID; k++) acc += hs[k] * wr[k];
    g_cbias[b * HID + o] = acc;
}

// ---------------- kernel 3: pipelined fp16 GEMM (2-term W split) + tanh + V-dot ----------------
// grid (4 nb, 16 st, 64 b); 256 threads = 8 warps (4 along M x 2 along N).
// CTA tile: M=128 (s), N=128 (o), K=512 in 8 double-buffered KC=64 stages.
__global__ __launch_bounds__(256, 2) void attn_main_kernel(const float* __restrict__ Vw) {
    extern __shared__ __align__(128) char smem[];
    const uint32_t sbase = smem_u32(smem);

    const int nb  = blockIdx.x;          // n-block fastest -> 4 CTAs share enc tile in L2
    const int st  = blockIdx.y;
    const int b   = blockIdx.z;
    const int tid = threadIdx.x;
    const int lane = tid & 31;
    const int wid  = tid >> 5;
    const int warp_m = wid & 3;
    const int warp_n = wid >> 2;
    const int s0 = st * 128;
    const int o0 = nb * 128;

    const __half* encRow = g_encH + (size_t)(b * SRC + s0) * HID;

    float acc[2][8][4];
#pragma unroll
    for (int i = 0; i < 2; i++)
#pragma unroll
        for (int j = 0; j < 8; j++)
#pragma unroll
            for (int r = 0; r < 4; r++) acc[i][j][r] = 0.f;

    // ---- stage loader: A (enc fp16 128xKC) + B hi/lo (W1 fp16 128xKC) ----
    auto load_stage = [&](int s, int kc) {
        const uint32_t tb = sbase + s * STG_BYTES;
#pragma unroll
        for (int i = 0; i < 4; ++i) {
            const int idx = tid + i * 256;          // 0..1023
            const int row = idx >> 3;               // 0..127
            const int u   = idx & 7;                // 16B unit (8 halves)
            const uint32_t doff = (uint32_t)(row * LDTB + u * 16);
            cp_async16(tb + doff, encRow + (size_t)row * HID + kc + u * 8);
            const size_t wof = (size_t)(o0 + row) * HID + kc + u * 8;
            cp_async16(tb + TILE_BYTES     + doff, g_W1hi + wof);
            cp_async16(tb + 2 * TILE_BYTES + doff, g_W1lo + wof);
        }
        cp_commit();
    };

    // ---- stage compute: 4 k16 steps ----
    auto compute_stage = [&](int s) {
        const uint32_t tb = sbase + s * STG_BYTES;
#pragma unroll
        for (int ks = 0; ks < KC; ks += 16) {
            uint32_t a[2][4];
#pragma unroll
            for (int mt = 0; mt < 2; mt++) {
                const int r = warp_m * 32 + mt * 16 + (lane & 15);
                const int c = ks + ((lane >> 4) << 3);
                ldsm4(a[mt], tb + (uint32_t)(r * LDTB + c * 2));
            }
#pragma unroll
            for (int ntp = 0; ntp < 4; ntp++) {
                const int br = warp_n * 64 + ntp * 16 + ((lane >> 4) << 3) + (lane & 7);
                const int bc = ks + (((lane >> 3) & 1) << 3);
                uint32_t bh[4], bl[4];
                ldsm4(bh, tb + TILE_BYTES     + (uint32_t)(br * LDTB + bc * 2));
                ldsm4(bl, tb + 2 * TILE_BYTES + (uint32_t)(br * LDTB + bc * 2));
#pragma unroll
                for (int mt = 0; mt < 2; mt++) {
#pragma unroll
                    for (int half = 0; half < 2; half++) {
                        float* c = acc[mt][ntp * 2 + half];
                        mma_fp16(c, a[mt], bh + 2 * half);
                        mma_fp16(c, a[mt], bl + 2 * half);
                    }
                }
            }
        }
    };

    // ---- double-buffered mainloop ----
    load_stage(0, 0);
#pragma unroll 1
    for (int it = 0; it < 8; ++it) {
        if (it < 7) {
            load_stage((it + 1) & 1, (it + 1) * KC);
            asm volatile("cp.async.wait_group 1;" ::: "memory");
        } else {
            asm volatile("cp.async.wait_group 0;" ::: "memory");
        }
        __syncthreads();
        compute_stage(it & 1);
        __syncthreads();    // protect buffer before it is refilled two stages later
    }

    // ---- epilogue: tanh(acc + cbias) * V, reduce over the 128 o-columns ----
    float rowsum[2][2];
    rowsum[0][0] = rowsum[0][1] = rowsum[1][0] = rowsum[1][1] = 0.f;

    const float* cbRow = g_cbias + b * HID;
#pragma unroll
    for (int nt = 0; nt < 8; nt++) {
        const int o = o0 + warp_n * 64 + nt * 8 + (lane & 3) * 2;
        const float cb0 = cbRow[o],     v0 = Vw[o];
        const float cb1 = cbRow[o + 1], v1 = Vw[o + 1];
#pragma unroll
        for (int mt = 0; mt < 2; mt++) {
            rowsum[mt][0] += tanhf(acc[mt][nt][0] + cb0) * v0;
            rowsum[mt][0] += tanhf(acc[mt][nt][1] + cb1) * v1;
            rowsum[mt][1] += tanhf(acc[mt][nt][2] + cb0) * v0;
            rowsum[mt][1] += tanhf(acc[mt][nt][3] + cb1) * v1;
        }
    }

    float* sRed = reinterpret_cast<float*>(smem);   // alias tile smem (mainloop done)
#pragma unroll
    for (int mt = 0; mt < 2; mt++) {
#pragma unroll
        for (int j = 0; j < 2; j++) {
            float v = rowsum[mt][j];
            v += __shfl_xor_sync(0xffffffffu, v, 1);
            v += __shfl_xor_sync(0xffffffffu, v, 2);
            if ((lane & 3) == 0) {
                const int row = warp_m * 32 + mt * 16 + (lane >> 2) + 8 * j;
                sRed[row * 2 + warp_n] = v;
            }
        }
    }
    __syncthreads();

    if (tid < 128) {
        g_part[nb][b][s0 + tid] = sRed[tid * 2] + sRed[tid * 2 + 1];
    }
}

// ---------------- kernel 4: sum partials + softmax over S ----------------
__global__ void softmax_kernel(float* __restrict__ out) {
    __shared__ float sv[SRC];
    __shared__ float red[256];
    int b = blockIdx.x;
    int tid = threadIdx.x;

    float mx = -1e30f;
    for (int s = tid; s < SRC; s += 256) {
        float v = g_part[0][b][s] + g_part[1][b][s] + g_part[2][b][s] + g_part[3][b][s];
        sv[s] = v;
        mx = fmaxf(mx, v);
    }
    red[tid] = mx;
    __syncthreads();
    for (int st = 128; st > 0; st >>= 1) {
        if (tid < st) red[tid] = fmaxf(red[tid], red[tid + st]);
        __syncthreads();
    }
    mx = red[0];
    __syncthreads();

    float sum = 0.f;
    for (int s = tid; s < SRC; s += 256) {
        float e = expf(sv[s] - mx);
        sv[s] = e;
        sum += e;
    }
    red[tid] = sum;
    __syncthreads();
    for (int st = 128; st > 0; st >>= 1) {
        if (tid < st) red[tid] += red[tid + st];
        __syncthreads();
    }
    float inv = 1.0f / red[0];
    __syncthreads();

    for (int s = tid; s < SRC; s += 256) {
        out[(size_t)b * SRC + s] = sv[s] * inv;
    }
}

// ---------------- launch ----------------
extern "C" void kernel_launch(void* const* d_in, const int* in_sizes, int n_in,
                              void* d_out, int out_size) {
    const float* h    = (const float*)d_in[0];   // [1, 64, 512]
    const float* enc  = (const float*)d_in[1];   // [64, 2048, 512]
    const float* W1w  = (const float*)d_in[2];   // [512, 512]
    const float* W1b  = (const float*)d_in[3];   // [512]
    const float* W2w  = (const float*)d_in[4];   // [512, 512]
    const float* W2b  = (const float*)d_in[5];   // [512]
    const float* Vw   = (const float*)d_in[6];   // [1, 512]
    // d_in[7] = V_b : softmax-invariant -> unused
    float* out = (float*)d_out;                  // [64, 2048]

    cudaFuncSetAttribute(attn_main_kernel,
                         cudaFuncAttributeMaxDynamicSharedMemorySize, SMEM_BYTES);

    prep_enc_kernel<<<8192, 256>>>(enc);
    prep_w_kernel<<<(HID * HID + 511) / 512, 512>>>(W1w);
    cbias_kernel<<<BATCH, HID>>>(h, W2w, W2b, W1b);
    attn_main_kernel<<<dim3(4, SRC / 128, BATCH), 256, SMEM_BYTES>>>(Vw);
    softmax_kernel<<<BATCH, 256>>>(out);
}

// round 8
// speedup vs baseline: 1.7697x; 1.3937x over previous
#include <cuda_runtime.h>
#include <cuda_fp16.h>
#include <cstdint>

#define HID   512
#define SRC   2048
#define BATCH 64

// main kernel tiling
#define KC    64                 // K per pipeline stage
#define LDT   72                 // halves per smem tile row (144B, conflict-free ldsm)
#define LDTB  (LDT * 2)          // 144 bytes
#define TILE_BYTES (128 * LDTB)  // 18432 B per 128-row tile
#define STG_BYTES  (2 * TILE_BYTES)   // A + B = 36864
#define NSTG  3
#define SMEM_BYTES (NSTG * STG_BYTES) // 110592 (3-stage ring)

// ---------------- device scratch (static, no runtime allocation) ----------------
__device__ __align__(16) __half g_encH[(size_t)BATCH * SRC * HID];  // 128 MB fp16 enc
__device__ __align__(16) __half g_W1h[HID * HID];
__device__ float g_cbias[BATCH * HID];          // W1_b + W2_b + h@W2^T
__device__ float g_part[4][BATCH][SRC];         // per-n-block partial scores

// ---------------- helpers ----------------
__device__ __forceinline__ unsigned smem_u32(const void* p) {
    return (unsigned)__cvta_generic_to_shared(p);
}
__device__ __forceinline__ void ldsm4(uint32_t r[4], unsigned addr) {
    asm volatile("ldmatrix.sync.aligned.m8n8.x4.shared.b16 {%0,%1,%2,%3}, [%4];"
                 : "=r"(r[0]), "=r"(r[1]), "=r"(r[2]), "=r"(r[3]) : "r"(addr));
}
__device__ __forceinline__ void mma_fp16(float c[4], const uint32_t a[4], const uint32_t b[2]) {
    asm volatile(
        "mma.sync.aligned.m16n8k16.row.col.f32.f16.f16.f32 "
        "{%0,%1,%2,%3}, {%4,%5,%6,%7}, {%8,%9}, {%0,%1,%2,%3};"
        : "+f"(c[0]), "+f"(c[1]), "+f"(c[2]), "+f"(c[3])
        : "r"(a[0]), "r"(a[1]), "r"(a[2]), "r"(a[3]), "r"(b[0]), "r"(b[1]));
}
__device__ __forceinline__ void cp_async16(uint32_t dst, const void* src) {
    asm volatile("cp.async.cg.shared.global [%0], [%1], 16;" :: "r"(dst), "l"(src) : "memory");
}
__device__ __forceinline__ void cp_commit() {
    asm volatile("cp.async.commit_group;" ::: "memory");
}

// ---------------- kernel 1a: convert enc fp32 -> fp16 ----------------
__global__ void prep_enc_kernel(const float* __restrict__ enc) {
    const size_t n4 = (size_t)BATCH * SRC * HID / 4;
    size_t i = (size_t)blockIdx.x * blockDim.x + threadIdx.x;
    const size_t stride = (size_t)gridDim.x * blockDim.x;
    for (; i < n4; i += stride) {
        float4 f = reinterpret_cast<const float4*>(enc)[i];
        __half2 h01 = __floats2half2_rn(f.x, f.y);
        __half2 h23 = __floats2half2_rn(f.z, f.w);
        uint2 u;
        u.x = *reinterpret_cast<uint32_t*>(&h01);
        u.y = *reinterpret_cast<uint32_t*>(&h23);
        reinterpret_cast<uint2*>(g_encH)[i] = u;
    }
}

// ---------------- kernel 1b: convert W1 -> fp16 ----------------
__global__ void prep_w_kernel(const float* __restrict__ W1w) {
    int i = blockIdx.x * blockDim.x + threadIdx.x;
    if (i < HID * HID) g_W1h[i] = __float2half_rn(W1w[i]);
}

// ---------------- kernel 2: cbias[b][o] = W1_b[o] + W2_b[o] + h[b]@W2[o] ----------------
__global__ void cbias_kernel(const float* __restrict__ h,
                             const float* __restrict__ W2w,
                             const float* __restrict__ W2b,
                             const float* __restrict__ W1b) {
    __shared__ float hs[HID];
    int b = blockIdx.x;
    int o = threadIdx.x;
    hs[o] = h[b * HID + o];
    __syncthreads();
    float acc = W2b[o] + W1b[o];
    const float* wr = W2w + o * HID;
#pragma unroll 8
    for (int k = 0; k < HID; k++) acc += hs[k] * wr[k];
    g_cbias[b * HID + o] = acc;
}

// ---------------- kernel 3: 3-stage pipelined fp16 GEMM + tanh + V-dot ----------------
// grid (4 nb, 16 st, 64 b); 256 threads = 8 warps (4 along M x 2 along N).
// CTA tile: M=128 (s), N=128 (o), K=512 in 8 KC=64 chunks, 3-deep cp.async ring.
__global__ __launch_bounds__(256, 2) void attn_main_kernel(const float* __restrict__ Vw) {
    extern __shared__ __align__(128) char smem[];
    const uint32_t sbase = smem_u32(smem);

    const int nb  = blockIdx.x;          // n-block fastest -> 4 CTAs share enc tile in L2
    const int st  = blockIdx.y;
    const int b   = blockIdx.z;
    const int tid = threadIdx.x;
    const int lane = tid & 31;
    const int wid  = tid >> 5;
    const int warp_m = wid & 3;
    const int warp_n = wid >> 2;
    const int s0 = st * 128;
    const int o0 = nb * 128;

    const __half* encRow = g_encH + (size_t)(b * SRC + s0) * HID;

    float acc[2][8][4];
#pragma unroll
    for (int i = 0; i < 2; i++)
#pragma unroll
        for (int j = 0; j < 8; j++)
#pragma unroll
            for (int r = 0; r < 4; r++) acc[i][j][r] = 0.f;

    // ---- stage loader: A (enc fp16 128xKC) + B (W1 fp16 128xKC) ----
    auto load_stage = [&](int s, int kc) {
        const uint32_t tb = sbase + s * STG_BYTES;
#pragma unroll
        for (int i = 0; i < 4; ++i) {
            const int idx = tid + i * 256;          // 0..1023
            const int row = idx >> 3;               // 0..127
            const int u   = idx & 7;                // 16B unit (8 halves)
            const uint32_t doff = (uint32_t)(row * LDTB + u * 16);
            cp_async16(tb + doff, encRow + (size_t)row * HID + kc + u * 8);
            cp_async16(tb + TILE_BYTES + doff,
                       g_W1h + (size_t)(o0 + row) * HID + kc + u * 8);
        }
        cp_commit();
    };

    // ---- stage compute: 4 k16 steps ----
    auto compute_stage = [&](int s) {
        const uint32_t tb = sbase + s * STG_BYTES;
#pragma unroll
        for (int ks = 0; ks < KC; ks += 16) {
            uint32_t a[2][4];
#pragma unroll
            for (int mt = 0; mt < 2; mt++) {
                const int r = warp_m * 32 + mt * 16 + (lane & 15);
                const int c = ks + ((lane >> 4) << 3);
                ldsm4(a[mt], tb + (uint32_t)(r * LDTB + c * 2));
            }
#pragma unroll
            for (int ntp = 0; ntp < 4; ntp++) {
                const int br = warp_n * 64 + ntp * 16 + ((lane >> 4) << 3) + (lane & 7);
                const int bc = ks + (((lane >> 3) & 1) << 3);
                uint32_t bh[4];
                ldsm4(bh, tb + TILE_BYTES + (uint32_t)(br * LDTB + bc * 2));
#pragma unroll
                for (int mt = 0; mt < 2; mt++) {
#pragma unroll
                    for (int half = 0; half < 2; half++) {
                        mma_fp16(acc[mt][ntp * 2 + half], a[mt], bh + 2 * half);
                    }
                }
            }
        }
    };

    // ---- 3-stage ring mainloop ----
    load_stage(0, 0);
    load_stage(1, KC);
#pragma unroll 1
    for (int it = 0; it < 8; ++it) {
        if (it == 7) {
            asm volatile("cp.async.wait_group 0;" ::: "memory");
        } else {
            asm volatile("cp.async.wait_group 1;" ::: "memory");
        }
        __syncthreads();
        compute_stage(it % NSTG);
        if (it + 2 < 8) load_stage((it + 2) % NSTG, (it + 2) * KC);
    }

    // ---- epilogue: tanh(acc + cbias) * V, reduce over the 128 o-columns ----
    float rowsum[2][2];
    rowsum[0][0] = rowsum[0][1] = rowsum[1][0] = rowsum[1][1] = 0.f;

    const float* cbRow = g_cbias + b * HID;
#pragma unroll
    for (int nt = 0; nt < 8; nt++) {
        const int o = o0 + warp_n * 64 + nt * 8 + (lane & 3) * 2;
        const float cb0 = cbRow[o],     v0 = Vw[o];
        const float cb1 = cbRow[o + 1], v1 = Vw[o + 1];
#pragma unroll
        for (int mt = 0; mt < 2; mt++) {
            rowsum[mt][0] += tanhf(acc[mt][nt][0] + cb0) * v0;
            rowsum[mt][0] += tanhf(acc[mt][nt][1] + cb1) * v1;
            rowsum[mt][1] += tanhf(acc[mt][nt][2] + cb0) * v0;
            rowsum[mt][1] += tanhf(acc[mt][nt][3] + cb1) * v1;
        }
    }

    // stage-0 buffer is idle since iter 6; all threads passed the iter-7 barrier
    float* sRed = reinterpret_cast<float*>(smem);
#pragma unroll
    for (int mt = 0; mt < 2; mt++) {
#pragma unroll
        for (int j = 0; j < 2; j++) {
            float v = rowsum[mt][j];
            v += __shfl_xor_sync(0xffffffffu, v, 1);
            v += __shfl_xor_sync(0xffffffffu, v, 2);
            if ((lane & 3) == 0) {
                const int row = warp_m * 32 + mt * 16 + (lane >> 2) + 8 * j;
                sRed[row * 2 + warp_n] = v;
            }
        }
    }
    __syncthreads();

    if (tid < 128) {
        g_part[nb][b][s0 + tid] = sRed[tid * 2] + sRed[tid * 2 + 1];
    }
}

// ---------------- kernel 4: sum partials + softmax over S ----------------
__global__ void softmax_kernel(float* __restrict__ out) {
    __shared__ float sv[SRC];
    __shared__ float red[256];
    int b = blockIdx.x;
    int tid = threadIdx.x;

    float mx = -1e30f;
    for (int s = tid; s < SRC; s += 256) {
        float v = g_part[0][b][s] + g_part[1][b][s] + g_part[2][b][s] + g_part[3][b][s];
        sv[s] = v;
        mx = fmaxf(mx, v);
    }
    red[tid] = mx;
    __syncthreads();
    for (int st = 128; st > 0; st >>= 1) {
        if (tid < st) red[tid] = fmaxf(red[tid], red[tid + st]);
        __syncthreads();
    }
    mx = red[0];
    __syncthreads();

    float sum = 0.f;
    for (int s = tid; s < SRC; s += 256) {
        float e = expf(sv[s] - mx);
        sv[s] = e;
        sum += e;
    }
    red[tid] = sum;
    __syncthreads();
    for (int st = 128; st > 0; st >>= 1) {
        if (tid < st) red[tid] += red[tid + st];
        __syncthreads();
    }
    float inv = 1.0f / red[0];
    __syncthreads();

    for (int s = tid; s < SRC; s += 256) {
        out[(size_t)b * SRC + s] = sv[s] * inv;
    }
}

// ---------------- launch ----------------
extern "C" void kernel_launch(void* const* d_in, const int* in_sizes, int n_in,
                              void* d_out, int out_size) {
    const float* h    = (const float*)d_in[0];   // [1, 64, 512]
    const float* enc  = (const float*)d_in[1];   // [64, 2048, 512]
    const float* W1w  = (const float*)d_in[2];   // [512, 512]
    const float* W1b  = (const float*)d_in[3];   // [512]
    const float* W2w  = (const float*)d_in[4];   // [512, 512]
    const float* W2b  = (const float*)d_in[5];   // [512]
    const float* Vw   = (const float*)d_in[6];   // [1, 512]
    // d_in[7] = V_b : softmax-invariant -> unused
    float* out = (float*)d_out;                  // [64, 2048]

    cudaFuncSetAttribute(attn_main_kernel,
                         cudaFuncAttributeMaxDynamicSharedMemorySize, SMEM_BYTES);

    prep_enc_kernel<<<16384, 256>>>(enc);
    prep_w_kernel<<<(HID * HID + 511) / 512, 512>>>(W1w);
    cbias_kernel<<<BATCH, HID>>>(h, W2w, W2b, W1b);
    attn_main_kernel<<<dim3(4, SRC / 128, BATCH), 256, SMEM_BYTES>>>(Vw);
    softmax_kernel<<<BATCH, 256>>>(out);
}

// round 9
// speedup vs baseline: 2.2411x; 1.2664x over previous
#include <cuda_runtime.h>
#include <cuda_fp16.h>
#include <cstdint>

#define HID   512
#define SRC   2048
#define BATCH 64

// main kernel tiling: CTA tile M=128, N=128, K=512 in 8 KC=64 stages
#define KC        64
#define A32_SLOT  32768                  // 128 rows x 64 fp32 (256B/row, linear)
#define B_SLOT    16384                  // 128 rows x 64 fp16 (128B/row, XOR-swizzled)
#define A16_SZ    16384                  // 128 rows x 64 fp16 (XOR-swizzled), single slot
#define OFF_A32   0
#define OFF_B     (2 * A32_SLOT)         // 65536
#define OFF_A16   (OFF_B + 2 * B_SLOT)   // 98304
#define SMEM_BYTES (OFF_A16 + A16_SZ)    // 114688 -> 2 CTAs/SM

// ---------------- device scratch (static, no runtime allocation) ----------------
__device__ __align__(16) __half g_W1h[HID * HID];
__device__ float g_cbias[BATCH * HID];          // W1_b + W2_b + h@W2^T
__device__ float g_part[4][BATCH][SRC];         // per-n-block partial scores

// ---------------- helpers ----------------
__device__ __forceinline__ unsigned smem_u32(const void* p) {
    return (unsigned)__cvta_generic_to_shared(p);
}
__device__ __forceinline__ void ldsm4(uint32_t r[4], unsigned addr) {
    asm volatile("ldmatrix.sync.aligned.m8n8.x4.shared.b16 {%0,%1,%2,%3}, [%4];"
                 : "=r"(r[0]), "=r"(r[1]), "=r"(r[2]), "=r"(r[3]) : "r"(addr));
}
__device__ __forceinline__ void mma_fp16(float c[4], const uint32_t a[4], const uint32_t b[2]) {
    asm volatile(
        "mma.sync.aligned.m16n8k16.row.col.f32.f16.f16.f32 "
        "{%0,%1,%2,%3}, {%4,%5,%6,%7}, {%8,%9}, {%0,%1,%2,%3};"
        : "+f"(c[0]), "+f"(c[1]), "+f"(c[2]), "+f"(c[3])
        : "r"(a[0]), "r"(a[1]), "r"(a[2]), "r"(a[3]), "r"(b[0]), "r"(b[1]));
}
__device__ __forceinline__ void cp_async16(uint32_t dst, const void* src) {
    asm volatile("cp.async.cg.shared.global [%0], [%1], 16;" :: "r"(dst), "l"(src) : "memory");
}
__device__ __forceinline__ void cp_commit() {
    asm volatile("cp.async.commit_group;" ::: "memory");
}

// ---------------- kernel 1: convert W1 -> fp16 ----------------
__global__ void prep_w_kernel(const float* __restrict__ W1w) {
    int i = blockIdx.x * blockDim.x + threadIdx.x;
    if (i < HID * HID) g_W1h[i] = __float2half_rn(W1w[i]);
}

// ---------------- kernel 2: cbias[b][o] = W1_b[o] + W2_b[o] + h[b]@W2[o] ----------------
__global__ void cbias_kernel(const float* __restrict__ h,
                             const float* __restrict__ W2w,
                             const float* __restrict__ W2b,
                             const float* __restrict__ W1b) {
    __shared__ float hs[HID];
    const int b = blockIdx.x;
    const int o = blockIdx.y * 128 + threadIdx.x;
    for (int k = threadIdx.x; k < HID; k += 128) hs[k] = h[b * HID + k];
    __syncthreads();
    float acc = W2b[o] + W1b[o];
    const float* wr = W2w + o * HID;
#pragma unroll 8
    for (int k = 0; k < HID; k++) acc += hs[k] * wr[k];
    g_cbias[b * HID + o] = acc;
}

// ---------------- kernel 3: fused fp32->fp16 + pipelined fp16 GEMM + tanh + V-dot ----------------
// grid (4 nb, 16 st, 64 b); 256 threads = 8 warps (4 along M x 2 along N).
__global__ __launch_bounds__(256, 2) void attn_main_kernel(const float* __restrict__ enc,
                                                           const float* __restrict__ Vw) {
    extern __shared__ __align__(128) char smem[];
    const uint32_t sb = smem_u32(smem);

    const int nb  = blockIdx.x;          // n-block fastest -> 4 CTAs share enc tile via L2
    const int st  = blockIdx.y;
    const int b   = blockIdx.z;
    const int tid = threadIdx.x;
    const int lane = tid & 31;
    const int wid  = tid >> 5;
    const int warp_m = wid & 3;
    const int warp_n = wid >> 2;
    const int s0 = st * 128;
    const int o0 = nb * 128;

    const float* encRow = enc + (size_t)(b * SRC + s0) * HID;

    float acc[2][8][4];
#pragma unroll
    for (int i = 0; i < 2; i++)
#pragma unroll
        for (int j = 0; j < 8; j++)
#pragma unroll
            for (int r = 0; r < 4; r++) acc[i][j][r] = 0.f;

    // ---- gmem stage loader: A fp32 (linear) + B fp16 (swizzled) ----
    auto load_gmem = [&](int slot, int kc) {
        const uint32_t a32 = sb + OFF_A32 + slot * A32_SLOT;
#pragma unroll
        for (int k = 0; k < 8; ++k) {
            const int q = tid + k * 256;          // 16B unit, 0..2047
            const int row = q >> 4;
            const int u   = q & 15;               // 4-float unit
            cp_async16(a32 + q * 16, encRow + (size_t)row * HID + kc + u * 4);
        }
        const uint32_t bb = sb + OFF_B + slot * B_SLOT;
#pragma unroll
        for (int k = 0; k < 4; ++k) {
            const int p = tid + k * 256;          // 16B unit, 0..1023
            const int row = p >> 3;
            const int u   = p & 7;                // 8-half unit
            cp_async16(bb + row * 128 + ((u ^ (row & 7)) << 4),
                       g_W1h + (size_t)(o0 + row) * HID + kc + u * 8);
        }
        cp_commit();
    };

    // ---- convert A fp32 smem -> fp16 swizzled smem ----
    auto convert_stage = [&](int slot) {
        const char* a32 = smem + OFF_A32 + slot * A32_SLOT;
        char* a16 = smem + OFF_A16;
#pragma unroll
        for (int k = 0; k < 8; ++k) {
            const int idx = tid + k * 256;        // float4 index, 0..2047
            const float4 f = *reinterpret_cast<const float4*>(a32 + idx * 16);
            __half2 h01 = __floats2half2_rn(f.x, f.y);
            __half2 h23 = __floats2half2_rn(f.z, f.w);
            const int row = idx >> 4;             // 16 float4 per row
            const int u8  = idx & 15;             // 8B unit within row
            const int u16 = u8 >> 1;
            uint2 v;
            v.x = *reinterpret_cast<uint32_t*>(&h01);
            v.y = *reinterpret_cast<uint32_t*>(&h23);
            *reinterpret_cast<uint2*>(a16 + row * 128 + ((u16 ^ (row & 7)) << 4)
                                      + (u8 & 1) * 8) = v;
        }
    };

    // ---- stage compute: 4 k16 steps, swizzled ldsm addressing ----
    auto compute_stage = [&](int bslot) {
        const uint32_t a16 = sb + OFF_A16;
        const uint32_t bb  = sb + OFF_B + bslot * B_SLOT;
#pragma unroll
        for (int ks = 0; ks < KC; ks += 16) {
            uint32_t a[2][4];
#pragma unroll
            for (int mt = 0; mt < 2; mt++) {
                const int r = warp_m * 32 + mt * 16 + (lane & 15);
                const int un = (ks >> 3) + (lane >> 4);
                ldsm4(a[mt], a16 + r * 128 + ((un ^ (r & 7)) << 4));
            }
#pragma unroll
            for (int ntp = 0; ntp < 4; ntp++) {
                const int br = warp_n * 64 + ntp * 16 + ((lane >> 4) << 3) + (lane & 7);
                const int bu = (ks >> 3) + ((lane >> 3) & 1);
                uint32_t bh[4];
                ldsm4(bh, bb + br * 128 + ((bu ^ (br & 7)) << 4));
#pragma unroll
                for (int mt = 0; mt < 2; mt++) {
#pragma unroll
                    for (int half = 0; half < 2; half++) {
                        mma_fp16(acc[mt][ntp * 2 + half], a[mt], bh + 2 * half);
                    }
                }
            }
        }
    };

    // ---- mainloop: one gmem group in flight, convert between two syncs ----
    load_gmem(0, 0);
#pragma unroll 1
    for (int it = 0; it < 8; ++it) {
        asm volatile("cp.async.wait_group 0;" ::: "memory");
        __syncthreads();                          // stage it arrived; compute(it-1) done
        if (it < 7) load_gmem((it + 1) & 1, (it + 1) * KC);
        convert_stage(it & 1);
        __syncthreads();                          // A16 ready
        compute_stage(it & 1);
    }

    // ---- epilogue: tanh(acc + cbias) * V, reduce over the 128 o-columns ----
    float rowsum[2][2];
    rowsum[0][0] = rowsum[0][1] = rowsum[1][0] = rowsum[1][1] = 0.f;

    const float* cbRow = g_cbias + b * HID;
#pragma unroll
    for (int nt = 0; nt < 8; nt++) {
        const int o = o0 + warp_n * 64 + nt * 8 + (lane & 3) * 2;
        const float cb0 = cbRow[o],     v0 = Vw[o];
        const float cb1 = cbRow[o + 1], v1 = Vw[o + 1];
#pragma unroll
        for (int mt = 0; mt < 2; mt++) {
            rowsum[mt][0] += tanhf(acc[mt][nt][0] + cb0) * v0;
            rowsum[mt][0] += tanhf(acc[mt][nt][1] + cb1) * v1;
            rowsum[mt][1] += tanhf(acc[mt][nt][2] + cb0) * v0;
            rowsum[mt][1] += tanhf(acc[mt][nt][3] + cb1) * v1;
        }
    }

    // sRed aliases the A32 slot-0 region (no reader after its last convert)
    float* sRed = reinterpret_cast<float*>(smem);
#pragma unroll
    for (int mt = 0; mt < 2; mt++) {
#pragma unroll
        for (int j = 0; j < 2; j++) {
            float v = rowsum[mt][j];
            v += __shfl_xor_sync(0xffffffffu, v, 1);
            v += __shfl_xor_sync(0xffffffffu, v, 2);
            if ((lane & 3) == 0) {
                const int row = warp_m * 32 + mt * 16 + (lane >> 2) + 8 * j;
                sRed[row * 2 + warp_n] = v;
            }
        }
    }
    __syncthreads();

    if (tid < 128) {
        g_part[nb][b][s0 + tid] = sRed[tid * 2] + sRed[tid * 2 + 1];
    }
}

// ---------------- kernel 4: sum partials + softmax over S ----------------
__global__ void softmax_kernel(float* __restrict__ out) {
    __shared__ float sv[SRC];
    __shared__ float red[256];
    int b = blockIdx.x;
    int tid = threadIdx.x;

    float mx = -1e30f;
    for (int s = tid; s < SRC; s += 256) {
        float v = g_part[0][b][s] + g_part[1][b][s] + g_part[2][b][s] + g_part[3][b][s];
        sv[s] = v;
        mx = fmaxf(mx, v);
    }
    red[tid] = mx;
    __syncthreads();
    for (int st = 128; st > 0; st >>= 1) {
        if (tid < st) red[tid] = fmaxf(red[tid], red[tid + st]);
        __syncthreads();
    }
    mx = red[0];
    __syncthreads();

    float sum = 0.f;
    for (int s = tid; s < SRC; s += 256) {
        float e = expf(sv[s] - mx);
        sv[s] = e;
        sum += e;
    }
    red[tid] = sum;
    __syncthreads();
    for (int st = 128; st > 0; st >>= 1) {
        if (tid < st) red[tid] += red[tid + st];
        __syncthreads();
    }
    float inv = 1.0f / red[0];
    __syncthreads();

    for (int s = tid; s < SRC; s += 256) {
        out[(size_t)b * SRC + s] = sv[s] * inv;
    }
}

// ---------------- launch ----------------
extern "C" void kernel_launch(void* const* d_in, const int* in_sizes, int n_in,
                              void* d_out, int out_size) {
    const float* h    = (const float*)d_in[0];   // [1, 64, 512]
    const float* enc  = (const float*)d_in[1];   // [64, 2048, 512]
    const float* W1w  = (const float*)d_in[2];   // [512, 512]
    const float* W1b  = (const float*)d_in[3];   // [512]
    const float* W2w  = (const float*)d_in[4];   // [512, 512]
    const float* W2b  = (const float*)d_in[5];   // [512]
    const float* Vw   = (const float*)d_in[6];   // [1, 512]
    // d_in[7] = V_b : softmax-invariant -> unused
    float* out = (float*)d_out;                  // [64, 2048]

    cudaFuncSetAttribute(attn_main_kernel,
                         cudaFuncAttributeMaxDynamicSharedMemorySize, SMEM_BYTES);

    prep_w_kernel<<<(HID * HID + 511) / 512, 512>>>(W1w);
    cbias_kernel<<<dim3(BATCH, 4), 128>>>(h, W2w, W2b, W1b);
    attn_main_kernel<<<dim3(4, SRC / 128, BATCH), 256, SMEM_BYTES>>>(enc, Vw);
    softmax_kernel<<<BATCH, 256>>>(out);
}